// round 7
// baseline (speedup 1.0000x reference)
#include <cuda_runtime.h>
#include <cstdint>

#define BB   64
#define LL   512
#define EE   128
#define CPG  256     // channels per kernel-size group
#define TCT  768     // total channels (3 groups)
#define OUTW 2304    // 3 segments * 768

// ---- scratch (static __device__: allocation-free) ----
__device__ __align__(16) float g_emb[BB * LL * EE];                  // gathered embeddings
__device__ __align__(16) float g_wT[(3 + 5 + 7) * EE * CPG];         // transposed weights [k][e][c]
__device__ int g_segpos[BB][3];                                      // first occurrence of tokens 1,2,3

static const int W3SZ = 3 * EE * CPG;   // 98304
static const int W5SZ = 5 * EE * CPG;   // 163840

// shared layout (uniform across K): As = 70 rows x 132; Ws double buffer after
#define AROWS_MAX 70
#define APAD      132
#define WS_OFF    (AROWS_MAX * APAD)                  // floats
#define SMEM_TOT  ((AROWS_MAX * APAD + 2 * 7 * 8 * 128) * 4)   // 94304 bytes

// --------------------------------------------------------------------------
// prep: segment boundaries + zero output (atomicMax base)
// --------------------------------------------------------------------------
__global__ void prep_kernel(const int* __restrict__ inp, float* __restrict__ out) {
    __shared__ int fpos[3];
    const int b = blockIdx.x;
    const int tid = threadIdx.x;
    if (tid < 3) fpos[tid] = LL - 1;
    __syncthreads();
    for (int l = tid; l < LL; l += blockDim.x) {
        int tok = inp[b * LL + l];
        if (tok >= 1 && tok <= 3) atomicMin(&fpos[tok - 1], l);
    }
    __syncthreads();
    if (tid < 3) g_segpos[b][tid] = fpos[tid];
    for (int i = tid; i < OUTW; i += blockDim.x) out[b * OUTW + i] = 0.0f;
}

// --------------------------------------------------------------------------
// gather: emb_weight[inputs] -> g_emb  (coalesced float4)
// --------------------------------------------------------------------------
__global__ void gather_kernel(const int* __restrict__ inp, const float* __restrict__ emb) {
    int idx = blockIdx.x * blockDim.x + threadIdx.x;   // over B*L*32 float4s
    int row = idx >> 5;
    int q = idx & 31;
    int tok = inp[row];
    reinterpret_cast<float4*>(g_emb)[idx] =
        reinterpret_cast<const float4*>(emb + (size_t)tok * EE)[q];
}

// --------------------------------------------------------------------------
// weight transpose: src[c][k][e] (c-major) -> g_wT[dstoff + (k*E+e)*CPG + c]
// --------------------------------------------------------------------------
__global__ void wtrans_kernel(const float* __restrict__ src, int KE, int dstoff) {
    int r = blockIdx.x;    // 0..KE-1  (= k*E+e)
    int c = threadIdx.x;   // 0..255
    g_wT[dstoff + r * CPG + c] = src[c * KE + r];
}

// --------------------------------------------------------------------------
// conv body (templated on K), called from the merged kernel
// thread (tx = tid&15, ty = tid>>4): 4 L-positions, 8 channels
// channels: j=0: 4tx{+0,1}; j=1: 4tx+2{..}; j=2: 64+4tx{..}; j=3: 64+4tx+2{..}
// --------------------------------------------------------------------------
template <int K>
__device__ __forceinline__ void conv_body(float* smem,
                                          const float* __restrict__ bias,
                                          float* __restrict__ out,
                                          int woff, int gbase,
                                          int lbase, int cbase, int b) {
    constexpr int LO = (K - 1) / 2;
    constexpr int AROWS = 64 + K - 1;
    constexpr int WCH = K * 8 * 128;          // floats per Ws buffer
    float* As = smem;
    float* Ws = smem + WS_OFF;                // 2 buffers of WCH
    const float* wT = g_wT + woff;

    const int tid = threadIdx.x;
    const int tx = tid & 15;
    const int ty = tid >> 4;
    const int ty4 = ty * 4;

    const int p1 = g_segpos[b][0], p2 = g_segpos[b][1], p3 = g_segpos[b][2];
    if (lbase > p3) return;                   // tile never pooled

    // --- stage embedding tile (halo, zero-padded) ---
    const float4* embr = reinterpret_cast<const float4*>(g_emb + (size_t)b * LL * EE);
    for (int i = tid; i < AROWS * 32; i += 256) {
        int r = i >> 5, q = i & 31;
        int gl = lbase - LO + r;
        float4 v = make_float4(0.f, 0.f, 0.f, 0.f);
        if (gl >= 0 && gl < LL) v = embr[gl * 32 + q];
        *reinterpret_cast<float4*>(&As[r * APAD + q * 4]) = v;
    }

    // --- stage first weight chunk (e0 = 0) into buffer 0 ---
    for (int i = tid; i < K * 8 * 32; i += 256) {
        int r = i >> 5, q = i & 31;
        int k = r >> 3, e8 = r & 7;
        float4 wv = *reinterpret_cast<const float4*>(
            &wT[(size_t)(k * EE + e8) * CPG + cbase + q * 4]);
        *reinterpret_cast<float4*>(&Ws[r * 128 + q * 4]) = wv;
    }

    unsigned long long acc[4][4];
#pragma unroll
    for (int mi = 0; mi < 4; mi++)
#pragma unroll
        for (int j = 0; j < 4; j++) acc[mi][j] = 0ull;

    __syncthreads();

    for (int ch = 0; ch < 16; ch++) {
        const int e0 = ch * 8;
        float* Wb = Ws + (ch & 1) * WCH;
        // prefetch next chunk into other buffer (overlaps with compute below)
        if (ch < 15) {
            float* Wn = Ws + ((ch + 1) & 1) * WCH;
            int en = e0 + 8;
            for (int i = tid; i < K * 8 * 32; i += 256) {
                int r = i >> 5, q = i & 31;
                int k = r >> 3, e8 = r & 7;
                float4 wv = *reinterpret_cast<const float4*>(
                    &wT[(size_t)(k * EE + en + e8) * CPG + cbase + q * 4]);
                *reinterpret_cast<float4*>(&Wn[r * 128 + q * 4]) = wv;
            }
        }

#pragma unroll
        for (int e8 = 0; e8 < 8; e8++) {
            unsigned long long a2[K + 3];
#pragma unroll
            for (int rr = 0; rr < K + 3; rr++) {
                float av = As[(ty4 + rr) * APAD + e0 + e8];
                asm("mov.b64 %0, {%1, %1};" : "=l"(a2[rr]) : "f"(av));
            }
#pragma unroll
            for (int k = 0; k < K; k++) {
                const ulonglong2* wrow =
                    reinterpret_cast<const ulonglong2*>(&Wb[(k * 8 + e8) * 128]);
                ulonglong2 w01 = wrow[tx];        // channels 4tx, 4tx+2 (pairs)
                ulonglong2 w23 = wrow[tx + 16];   // channels 64+4tx, 64+4tx+2
                unsigned long long b2[4] = {w01.x, w01.y, w23.x, w23.y};
#pragma unroll
                for (int mi = 0; mi < 4; mi++)
#pragma unroll
                    for (int j = 0; j < 4; j++)
                        asm("fma.rn.f32x2 %0, %1, %2, %0;"
                            : "+l"(acc[mi][j])
                            : "l"(a2[mi + k]), "l"(b2[j]));
            }
        }
        __syncthreads();
    }

    // --- epilogue: bias + relu, segmented max into smem, global atomicMax ---
    int* segm = reinterpret_cast<int*>(smem);      // 3*128 ints, reuses As
    for (int i = tid; i < 3 * 128; i += 256) segm[i] = 0;

    int slo[3] = {0, p1, p2};
    int shi[3] = {p1, p2, p3};
    __syncthreads();

#pragma unroll
    for (int j = 0; j < 4; j++) {
        int cl0 = ((j >> 1) << 6) + 4 * tx + ((j & 1) << 1);
        float b0 = bias[cbase + cl0], b1 = bias[cbase + cl0 + 1];
        float vx[4], vy[4];
#pragma unroll
        for (int mi = 0; mi < 4; mi++) {
            float x, y;
            asm("mov.b64 {%0, %1}, %2;" : "=f"(x), "=f"(y) : "l"(acc[mi][j]));
            vx[mi] = fmaxf(x + b0, 0.0f);
            vy[mi] = fmaxf(y + b1, 0.0f);
        }
#pragma unroll
        for (int t = 0; t < 3; t++) {
            float mx = -1.0f, my = -1.0f;
            bool any = false;
#pragma unroll
            for (int mi = 0; mi < 4; mi++) {
                int l = lbase + ty4 + mi;
                bool in = (l >= slo[t] && l <= shi[t]);
                if (in) { mx = fmaxf(mx, vx[mi]); my = fmaxf(my, vy[mi]); any = true; }
            }
            if (any) {
                if (mx > 0.0f) atomicMax(&segm[t * 128 + cl0], __float_as_int(mx));
                if (my > 0.0f) atomicMax(&segm[t * 128 + cl0 + 1], __float_as_int(my));
            }
        }
    }
    __syncthreads();
    for (int i = tid; i < 3 * 128; i += 256) {
        int t = i >> 7, c = i & 127;
        if (segm[i] != 0)
            atomicMax(reinterpret_cast<int*>(&out[(size_t)b * OUTW + t * TCT + gbase + cbase + c]),
                      segm[i]);
    }
}

// --------------------------------------------------------------------------
// merged conv kernel: grid (8 Ltiles, 2 Ctiles, 192 = 64 b x 3 groups)
// --------------------------------------------------------------------------
__global__ void __launch_bounds__(256, 2) conv_all(const float* __restrict__ b3,
                                                   const float* __restrict__ b5,
                                                   const float* __restrict__ b7,
                                                   float* __restrict__ out) {
    extern __shared__ float smem[];
    const int lbase = blockIdx.x * 64;
    const int cbase = blockIdx.y * 128;
    const int g = blockIdx.z % 3;
    const int b = blockIdx.z / 3;

    if (g == 0)      conv_body<3>(smem, b3, out, 0,            0,   lbase, cbase, b);
    else if (g == 1) conv_body<5>(smem, b5, out, W3SZ,         256, lbase, cbase, b);
    else             conv_body<7>(smem, b7, out, W3SZ + W5SZ,  512, lbase, cbase, b);
}

// --------------------------------------------------------------------------
extern "C" void kernel_launch(void* const* d_in, const int* in_sizes, int n_in,
                              void* d_out, int out_size) {
    // map by element count; positional fallback
    const int* inp = nullptr;
    const float *emb = nullptr, *w3 = nullptr, *w5 = nullptr, *w7 = nullptr;
    const float* biases[3] = {nullptr, nullptr, nullptr};
    int nb = 0;
    for (int i = 0; i < n_in; i++) {
        switch (in_sizes[i]) {
            case 32768:   inp = (const int*)d_in[i];   break;
            case 6400000: emb = (const float*)d_in[i]; break;
            case 98304:   w3 = (const float*)d_in[i];  break;
            case 163840:  w5 = (const float*)d_in[i];  break;
            case 229376:  w7 = (const float*)d_in[i];  break;
            case 256:     if (nb < 3) biases[nb++] = (const float*)d_in[i]; break;
            default: break;
        }
    }
    if (!inp || !emb || !w3 || !w5 || !w7 || nb != 3) {
        inp = (const int*)d_in[0];
        emb = (const float*)d_in[1];
        w3 = (const float*)d_in[2];  biases[0] = (const float*)d_in[3];
        w5 = (const float*)d_in[4];  biases[1] = (const float*)d_in[5];
        w7 = (const float*)d_in[6];  biases[2] = (const float*)d_in[7];
    }
    float* out = (float*)d_out;
    (void)out_size;

    cudaFuncSetAttribute(conv_all, cudaFuncAttributeMaxDynamicSharedMemorySize, SMEM_TOT);

    prep_kernel<<<BB, 256>>>(inp, out);
    gather_kernel<<<(BB * LL * 32) / 256, 256>>>(inp, emb);
    wtrans_kernel<<<3 * EE, 256>>>(w3, 3 * EE, 0);
    wtrans_kernel<<<5 * EE, 256>>>(w5, 5 * EE, W3SZ);
    wtrans_kernel<<<7 * EE, 256>>>(w7, 7 * EE, W3SZ + W5SZ);

    conv_all<<<dim3(8, 2, 192), 256, SMEM_TOT>>>(biases[0], biases[1], biases[2], out);
}

// round 8
// speedup vs baseline: 1.4998x; 1.4998x over previous
#include <cuda_runtime.h>
#include <cstdint>

#define BB   64
#define LL   512
#define EE   128
#define CPG  256     // channels per kernel-size group
#define TCT  768     // total channels (3 groups)
#define OUTW 2304    // 3 segments * 768

// ---- scratch (static __device__: allocation-free) ----
__device__ __align__(16) float g_emb[BB * LL * EE];                  // gathered embeddings
__device__ __align__(16) float g_wT[(3 + 5 + 7) * EE * CPG];         // transposed weights [k][e][c]
__device__ int g_segpos[BB][3];                                      // first occurrence of tokens 1,2,3

static const int W3SZ = 3 * EE * CPG;   // 98304
static const int W5SZ = 5 * EE * CPG;   // 163840

// --------------------------------------------------------------------------
// prep: segment boundaries + zero output (atomicMax base)
// --------------------------------------------------------------------------
__global__ void prep_kernel(const int* __restrict__ inp, float* __restrict__ out) {
    __shared__ int fpos[3];
    const int b = blockIdx.x;
    const int tid = threadIdx.x;
    if (tid < 3) fpos[tid] = LL - 1;
    __syncthreads();
    for (int l = tid; l < LL; l += blockDim.x) {
        int tok = inp[b * LL + l];
        if (tok >= 1 && tok <= 3) atomicMin(&fpos[tok - 1], l);
    }
    __syncthreads();
    if (tid < 3) g_segpos[b][tid] = fpos[tid];
    for (int i = tid; i < OUTW; i += blockDim.x) out[b * OUTW + i] = 0.0f;
}

// --------------------------------------------------------------------------
// gather: emb_weight[inputs] -> g_emb  (coalesced float4)
// --------------------------------------------------------------------------
__global__ void gather_kernel(const int* __restrict__ inp, const float* __restrict__ emb) {
    int idx = blockIdx.x * blockDim.x + threadIdx.x;   // over B*L*32 float4s
    int row = idx >> 5;
    int q = idx & 31;
    int tok = inp[row];
    reinterpret_cast<float4*>(g_emb)[idx] =
        reinterpret_cast<const float4*>(emb + (size_t)tok * EE)[q];
}

// --------------------------------------------------------------------------
// weight transpose: src[c][k][e] (c-major) -> g_wT[dstoff + (k*E+e)*CPG + c]
// --------------------------------------------------------------------------
__global__ void wtrans_kernel(const float* __restrict__ src, int KE, int dstoff) {
    int r = blockIdx.x;    // 0..KE-1  (= k*E+e)
    int c = threadIdx.x;   // 0..255
    g_wT[dstoff + r * CPG + c] = src[c * KE + r];
}

// --------------------------------------------------------------------------
// conv + bias + relu + fused segmented max  (f32x2 packed FFMA mainloop)
// grid: (Ltiles=8, Ctiles=2, B=64), 256 threads
// thread (tx = tid&15, ty = tid>>4): 4 L-positions (ty*4+mi), 8 channels
// channels via ulonglong2: j=0: c=4tx{+0,1}; j=1: 4tx+2{..}; j=2: 64+4tx{..}; j=3: 64+4tx+2{..}
// --------------------------------------------------------------------------
template <int K>
__global__ void __launch_bounds__(256) conv_kernel(const float* __restrict__ bias,
                                                   float* __restrict__ out,
                                                   int woff, int gbase) {
    constexpr int LO = (K - 1) / 2;
    constexpr int AROWS = 64 + K - 1;
    constexpr int APAD = 132;            // 132*4 = 528 B rows: 16B aligned, bank-shifted
    extern __shared__ float smem[];
    float* As = smem;                    // AROWS x APAD
    float* Ws = smem + AROWS * APAD;     // (K*8) x 128
    const float* wT = g_wT + woff;

    const int tid = threadIdx.x;
    const int tx = tid & 15;
    const int ty = tid >> 4;
    const int ty4 = ty * 4;
    const int lbase = blockIdx.x * 64;
    const int cbase = blockIdx.y * 128;
    const int b = blockIdx.z;

    const int p1 = g_segpos[b][0], p2 = g_segpos[b][1], p3 = g_segpos[b][2];
    if (lbase > p3) return;              // tile entirely past last separator: never pooled

    // --- stage embedding tile (with halo, zero-padded at sequence ends) ---
    const float4* embr = reinterpret_cast<const float4*>(g_emb + (size_t)b * LL * EE);
    for (int i = tid; i < AROWS * 32; i += 256) {
        int r = i >> 5, q = i & 31;
        int gl = lbase - LO + r;
        float4 v = make_float4(0.f, 0.f, 0.f, 0.f);
        if (gl >= 0 && gl < LL) v = embr[gl * 32 + q];
        *reinterpret_cast<float4*>(&As[r * APAD + q * 4]) = v;
    }

    unsigned long long acc[4][4];
#pragma unroll
    for (int mi = 0; mi < 4; mi++)
#pragma unroll
        for (int j = 0; j < 4; j++) acc[mi][j] = 0ull;

    for (int e0 = 0; e0 < EE; e0 += 8) {
        __syncthreads();
        // stage weight chunk: Ws[(k*8+e8)*128 + c] = wT[(k*E + e0+e8)*CPG + cbase + c]
        for (int i = tid; i < K * 8 * 32; i += 256) {
            int r = i >> 5, q = i & 31;       // r = k*8 + e8
            int k = r >> 3, e8 = r & 7;
            float4 wv = *reinterpret_cast<const float4*>(
                &wT[(size_t)(k * EE + e0 + e8) * CPG + cbase + q * 4]);
            *reinterpret_cast<float4*>(&Ws[r * 128 + q * 4]) = wv;
        }
        __syncthreads();

#pragma unroll
        for (int e8 = 0; e8 < 8; e8++) {
            // a values: rows ty4 .. ty4+3+K-1 at column e0+e8, duplicated into f32x2
            unsigned long long a2[K + 3];
#pragma unroll
            for (int rr = 0; rr < K + 3; rr++) {
                float av = As[(ty4 + rr) * APAD + e0 + e8];
                asm("mov.b64 %0, {%1, %1};" : "=l"(a2[rr]) : "f"(av));
            }
#pragma unroll
            for (int k = 0; k < K; k++) {
                const ulonglong2* wrow =
                    reinterpret_cast<const ulonglong2*>(&Ws[(k * 8 + e8) * 128]);
                ulonglong2 w01 = wrow[tx];        // channel pairs 4tx, 4tx+2
                ulonglong2 w23 = wrow[tx + 16];   // channel pairs 64+4tx, 64+4tx+2
                unsigned long long b2[4] = {w01.x, w01.y, w23.x, w23.y};
#pragma unroll
                for (int mi = 0; mi < 4; mi++)
#pragma unroll
                    for (int j = 0; j < 4; j++)
                        asm("fma.rn.f32x2 %0, %1, %2, %0;"
                            : "+l"(acc[mi][j])
                            : "l"(a2[mi + k]), "l"(b2[j]));
            }
        }
    }

    // --- epilogue: bias + relu, segmented max into smem, then global atomicMax ---
    __syncthreads();                       // done reading As/Ws
    int* segm = reinterpret_cast<int*>(smem);   // 3 * 128 ints, reuses As
    for (int i = tid; i < 3 * 128; i += 256) segm[i] = 0;

    int slo[3] = {0, p1, p2};
    int shi[3] = {p1, p2, p3};
    __syncthreads();                       // segm init visible

#pragma unroll
    for (int j = 0; j < 4; j++) {
        int cl0 = ((j >> 1) << 6) + 4 * tx + ((j & 1) << 1);   // local channel of pair lo
        float b0 = bias[cbase + cl0], b1 = bias[cbase + cl0 + 1];
        float vx[4], vy[4];
#pragma unroll
        for (int mi = 0; mi < 4; mi++) {
            float x, y;
            asm("mov.b64 {%0, %1}, %2;" : "=f"(x), "=f"(y) : "l"(acc[mi][j]));
            vx[mi] = fmaxf(x + b0, 0.0f);
            vy[mi] = fmaxf(y + b1, 0.0f);
        }
#pragma unroll
        for (int t = 0; t < 3; t++) {
            float mx = -1.0f, my = -1.0f;
            bool any = false;
#pragma unroll
            for (int mi = 0; mi < 4; mi++) {
                int l = lbase + ty4 + mi;
                bool in = (l >= slo[t] && l <= shi[t]);
                if (in) { mx = fmaxf(mx, vx[mi]); my = fmaxf(my, vy[mi]); any = true; }
            }
            if (any) {
                if (mx > 0.0f) atomicMax(&segm[t * 128 + cl0], __float_as_int(mx));
                if (my > 0.0f) atomicMax(&segm[t * 128 + cl0 + 1], __float_as_int(my));
            }
        }
    }
    __syncthreads();
    for (int i = tid; i < 3 * 128; i += 256) {
        int t = i >> 7, c = i & 127;
        if (segm[i] != 0)
            atomicMax(reinterpret_cast<int*>(&out[(size_t)b * OUTW + t * TCT + gbase + cbase + c]),
                      segm[i]);
    }
}

// --------------------------------------------------------------------------
extern "C" void kernel_launch(void* const* d_in, const int* in_sizes, int n_in,
                              void* d_out, int out_size) {
    // map by element count; positional fallback
    const int* inp = nullptr;
    const float *emb = nullptr, *w3 = nullptr, *w5 = nullptr, *w7 = nullptr;
    const float* biases[3] = {nullptr, nullptr, nullptr};
    int nb = 0;
    for (int i = 0; i < n_in; i++) {
        switch (in_sizes[i]) {
            case 32768:   inp = (const int*)d_in[i];   break;
            case 6400000: emb = (const float*)d_in[i]; break;
            case 98304:   w3 = (const float*)d_in[i];  break;
            case 163840:  w5 = (const float*)d_in[i];  break;
            case 229376:  w7 = (const float*)d_in[i];  break;
            case 256:     if (nb < 3) biases[nb++] = (const float*)d_in[i]; break;
            default: break;
        }
    }
    if (!inp || !emb || !w3 || !w5 || !w7 || nb != 3) {
        inp = (const int*)d_in[0];
        emb = (const float*)d_in[1];
        w3 = (const float*)d_in[2];  biases[0] = (const float*)d_in[3];
        w5 = (const float*)d_in[4];  biases[1] = (const float*)d_in[5];
        w7 = (const float*)d_in[6];  biases[2] = (const float*)d_in[7];
    }
    const float* b3 = biases[0];
    const float* b5 = biases[1];
    const float* b7 = biases[2];
    float* out = (float*)d_out;
    (void)out_size;

    const int smem3 = (66 * 132 + 3 * 8 * 128) * 4;   // 47136
    const int smem5 = (68 * 132 + 5 * 8 * 128) * 4;   // 56384
    const int smem7 = (70 * 132 + 7 * 8 * 128) * 4;   // 65632
    cudaFuncSetAttribute(conv_kernel<3>, cudaFuncAttributeMaxDynamicSharedMemorySize, smem3);
    cudaFuncSetAttribute(conv_kernel<5>, cudaFuncAttributeMaxDynamicSharedMemorySize, smem5);
    cudaFuncSetAttribute(conv_kernel<7>, cudaFuncAttributeMaxDynamicSharedMemorySize, smem7);

    prep_kernel<<<BB, 256>>>(inp, out);
    gather_kernel<<<(BB * LL * 32) / 256, 256>>>(inp, emb);
    wtrans_kernel<<<3 * EE, 256>>>(w3, 3 * EE, 0);
    wtrans_kernel<<<5 * EE, 256>>>(w5, 5 * EE, W3SZ);
    wtrans_kernel<<<7 * EE, 256>>>(w7, 7 * EE, W3SZ + W5SZ);

    dim3 grid(8, 2, BB);
    conv_kernel<3><<<grid, 256, smem3>>>(b3, out, 0, 0);
    conv_kernel<5><<<grid, 256, smem5>>>(b5, out, W3SZ, 256);
    conv_kernel<7><<<grid, 256, smem7>>>(b7, out, W3SZ + W5SZ, 512);
}

// round 9
// speedup vs baseline: 1.7123x; 1.1416x over previous
#include <cuda_runtime.h>
#include <cstdint>

#define BB   64
#define LL   512
#define EE   128
#define CPG  256     // channels per kernel-size group
#define TCT  768     // total channels (3 groups)
#define OUTW 2304    // 3 segments * 768

// ---- scratch (static __device__: allocation-free) ----
__device__ __align__(16) float g_emb[BB * LL * EE];                  // gathered embeddings
__device__ __align__(16) float g_wT[(3 + 5 + 7) * EE * CPG];         // transposed weights [k][e][c]
__device__ int g_segpos[BB][3];                                      // first occurrence of tokens 1,2,3

static const int W3SZ = 3 * EE * CPG;   // 98304
static const int W5SZ = 5 * EE * CPG;   // 163840

// uniform shared layout: As = 70 rows x 132 floats, then Ws (<= 7*8*128 floats)
#define APAD    132
#define WS_OFF  (70 * APAD)                         // 9240 floats
#define SMEM_TOT ((70 * APAD + 7 * 8 * 128) * 4)    // 65632 bytes

// --------------------------------------------------------------------------
// prep: segment boundaries + zero output (atomicMax base)
// --------------------------------------------------------------------------
__global__ void prep_kernel(const int* __restrict__ inp, float* __restrict__ out) {
    __shared__ int fpos[3];
    const int b = blockIdx.x;
    const int tid = threadIdx.x;
    if (tid < 3) fpos[tid] = LL - 1;
    __syncthreads();
    for (int l = tid; l < LL; l += blockDim.x) {
        int tok = inp[b * LL + l];
        if (tok >= 1 && tok <= 3) atomicMin(&fpos[tok - 1], l);
    }
    __syncthreads();
    if (tid < 3) g_segpos[b][tid] = fpos[tid];
    for (int i = tid; i < OUTW; i += blockDim.x) out[b * OUTW + i] = 0.0f;
}

// --------------------------------------------------------------------------
// gather: emb_weight[inputs] -> g_emb  (coalesced float4)
// --------------------------------------------------------------------------
__global__ void gather_kernel(const int* __restrict__ inp, const float* __restrict__ emb) {
    int idx = blockIdx.x * blockDim.x + threadIdx.x;   // over B*L*32 float4s
    int row = idx >> 5;
    int q = idx & 31;
    int tok = inp[row];
    reinterpret_cast<float4*>(g_emb)[idx] =
        reinterpret_cast<const float4*>(emb + (size_t)tok * EE)[q];
}

// --------------------------------------------------------------------------
// weight transpose: src[c][k][e] (c-major) -> g_wT[dstoff + (k*E+e)*CPG + c]
// --------------------------------------------------------------------------
__global__ void wtrans_kernel(const float* __restrict__ src, int KE, int dstoff) {
    int r = blockIdx.x;    // 0..KE-1  (= k*E+e)
    int c = threadIdx.x;   // 0..255
    g_wT[dstoff + r * CPG + c] = src[c * KE + r];
}

// --------------------------------------------------------------------------
// conv body (identical math to R8's proven kernel), single weight buffer
// thread (tx = tid&15, ty = tid>>4): 4 L-positions, 8 channels
// --------------------------------------------------------------------------
template <int K>
__device__ __forceinline__ void conv_body(float* smem,
                                          const float* __restrict__ bias,
                                          float* __restrict__ out,
                                          int woff, int gbase,
                                          int lbase, int cbase, int b) {
    constexpr int LO = (K - 1) / 2;
    constexpr int AROWS = 64 + K - 1;
    float* As = smem;
    float* Ws = smem + WS_OFF;
    const float* wT = g_wT + woff;

    const int tid = threadIdx.x;
    const int tx = tid & 15;
    const int ty = tid >> 4;
    const int ty4 = ty * 4;

    const int p1 = g_segpos[b][0], p2 = g_segpos[b][1], p3 = g_segpos[b][2];
    if (lbase > p3) return;              // tile never pooled

    // --- stage embedding tile (halo, zero-padded) ---
    const float4* embr = reinterpret_cast<const float4*>(g_emb + (size_t)b * LL * EE);
    for (int i = tid; i < AROWS * 32; i += 256) {
        int r = i >> 5, q = i & 31;
        int gl = lbase - LO + r;
        float4 v = make_float4(0.f, 0.f, 0.f, 0.f);
        if (gl >= 0 && gl < LL) v = embr[gl * 32 + q];
        *reinterpret_cast<float4*>(&As[r * APAD + q * 4]) = v;
    }

    unsigned long long acc[4][4];
#pragma unroll
    for (int mi = 0; mi < 4; mi++)
#pragma unroll
        for (int j = 0; j < 4; j++) acc[mi][j] = 0ull;

    for (int e0 = 0; e0 < EE; e0 += 8) {
        __syncthreads();
        for (int i = tid; i < K * 8 * 32; i += 256) {
            int r = i >> 5, q = i & 31;       // r = k*8 + e8
            int k = r >> 3, e8 = r & 7;
            float4 wv = *reinterpret_cast<const float4*>(
                &wT[(size_t)(k * EE + e0 + e8) * CPG + cbase + q * 4]);
            *reinterpret_cast<float4*>(&Ws[r * 128 + q * 4]) = wv;
        }
        __syncthreads();

#pragma unroll
        for (int e8 = 0; e8 < 8; e8++) {
            unsigned long long a2[K + 3];
#pragma unroll
            for (int rr = 0; rr < K + 3; rr++) {
                float av = As[(ty4 + rr) * APAD + e0 + e8];
                asm("mov.b64 %0, {%1, %1};" : "=l"(a2[rr]) : "f"(av));
            }
#pragma unroll
            for (int k = 0; k < K; k++) {
                const ulonglong2* wrow =
                    reinterpret_cast<const ulonglong2*>(&Ws[(k * 8 + e8) * 128]);
                ulonglong2 w01 = wrow[tx];        // channel pairs 4tx, 4tx+2
                ulonglong2 w23 = wrow[tx + 16];   // channel pairs 64+4tx, 64+4tx+2
                unsigned long long b2[4] = {w01.x, w01.y, w23.x, w23.y};
#pragma unroll
                for (int mi = 0; mi < 4; mi++)
#pragma unroll
                    for (int j = 0; j < 4; j++)
                        asm("fma.rn.f32x2 %0, %1, %2, %0;"
                            : "+l"(acc[mi][j])
                            : "l"(a2[mi + k]), "l"(b2[j]));
            }
        }
    }

    // --- epilogue: bias + relu, segmented max into smem, global atomicMax ---
    __syncthreads();
    int* segm = reinterpret_cast<int*>(smem);
    for (int i = tid; i < 3 * 128; i += 256) segm[i] = 0;

    int slo[3] = {0, p1, p2};
    int shi[3] = {p1, p2, p3};
    __syncthreads();

#pragma unroll
    for (int j = 0; j < 4; j++) {
        int cl0 = ((j >> 1) << 6) + 4 * tx + ((j & 1) << 1);
        float b0 = bias[cbase + cl0], b1 = bias[cbase + cl0 + 1];
        float vx[4], vy[4];
#pragma unroll
        for (int mi = 0; mi < 4; mi++) {
            float x, y;
            asm("mov.b64 {%0, %1}, %2;" : "=f"(x), "=f"(y) : "l"(acc[mi][j]));
            vx[mi] = fmaxf(x + b0, 0.0f);
            vy[mi] = fmaxf(y + b1, 0.0f);
        }
#pragma unroll
        for (int t = 0; t < 3; t++) {
            float mx = -1.0f, my = -1.0f;
            bool any = false;
#pragma unroll
            for (int mi = 0; mi < 4; mi++) {
                int l = lbase + ty4 + mi;
                bool in = (l >= slo[t] && l <= shi[t]);
                if (in) { mx = fmaxf(mx, vx[mi]); my = fmaxf(my, vy[mi]); any = true; }
            }
            if (any) {
                if (mx > 0.0f) atomicMax(&segm[t * 128 + cl0], __float_as_int(mx));
                if (my > 0.0f) atomicMax(&segm[t * 128 + cl0 + 1], __float_as_int(my));
            }
        }
    }
    __syncthreads();
    for (int i = tid; i < 3 * 128; i += 256) {
        int t = i >> 7, c = i & 127;
        if (segm[i] != 0)
            atomicMax(reinterpret_cast<int*>(&out[(size_t)b * OUTW + t * TCT + gbase + cbase + c]),
                      segm[i]);
    }
}

// --------------------------------------------------------------------------
// merged conv: grid (8 Ltiles, 2 Ctiles, 192 = b*3 + g), one launch, ~10 waves
// --------------------------------------------------------------------------
__global__ void __launch_bounds__(256, 3) conv_all(const float* __restrict__ b3,
                                                   const float* __restrict__ b5,
                                                   const float* __restrict__ b7,
                                                   float* __restrict__ out) {
    extern __shared__ float smem[];
    const int lbase = blockIdx.x * 64;
    const int cbase = blockIdx.y * 128;
    const int g = blockIdx.z % 3;
    const int b = blockIdx.z / 3;

    if (g == 0)      conv_body<3>(smem, b3, out, 0,           0,   lbase, cbase, b);
    else if (g == 1) conv_body<5>(smem, b5, out, W3SZ,        256, lbase, cbase, b);
    else             conv_body<7>(smem, b7, out, W3SZ + W5SZ, 512, lbase, cbase, b);
}

// --------------------------------------------------------------------------
extern "C" void kernel_launch(void* const* d_in, const int* in_sizes, int n_in,
                              void* d_out, int out_size) {
    // map by element count; positional fallback
    const int* inp = nullptr;
    const float *emb = nullptr, *w3 = nullptr, *w5 = nullptr, *w7 = nullptr;
    const float* biases[3] = {nullptr, nullptr, nullptr};
    int nb = 0;
    for (int i = 0; i < n_in; i++) {
        switch (in_sizes[i]) {
            case 32768:   inp = (const int*)d_in[i];   break;
            case 6400000: emb = (const float*)d_in[i]; break;
            case 98304:   w3 = (const float*)d_in[i];  break;
            case 163840:  w5 = (const float*)d_in[i];  break;
            case 229376:  w7 = (const float*)d_in[i];  break;
            case 256:     if (nb < 3) biases[nb++] = (const float*)d_in[i]; break;
            default: break;
        }
    }
    if (!inp || !emb || !w3 || !w5 || !w7 || nb != 3) {
        inp = (const int*)d_in[0];
        emb = (const float*)d_in[1];
        w3 = (const float*)d_in[2];  biases[0] = (const float*)d_in[3];
        w5 = (const float*)d_in[4];  biases[1] = (const float*)d_in[5];
        w7 = (const float*)d_in[6];  biases[2] = (const float*)d_in[7];
    }
    float* out = (float*)d_out;
    (void)out_size;

    cudaFuncSetAttribute(conv_all, cudaFuncAttributeMaxDynamicSharedMemorySize, SMEM_TOT);

    prep_kernel<<<BB, 256>>>(inp, out);
    gather_kernel<<<(BB * LL * 32) / 256, 256>>>(inp, emb);
    wtrans_kernel<<<3 * EE, 256>>>(w3, 3 * EE, 0);
    wtrans_kernel<<<5 * EE, 256>>>(w5, 5 * EE, W3SZ);
    wtrans_kernel<<<7 * EE, 256>>>(w7, 7 * EE, W3SZ + W5SZ);

    conv_all<<<dim3(8, 2, 192), 256, SMEM_TOT>>>(biases[0], biases[1], biases[2], out);
}